// round 1
// baseline (speedup 1.0000x reference)
#include <cuda_runtime.h>
#include <math.h>

#define NN 512
#define CC 3
#define PIX 1024
#define FF 3072          // C*IMG*IMG
#define HH 4
#define HF 12288         // HEADS*F
#define EE 4096
#define ET 4608          // E + N self loops
#define BEPS 1e-5f
#define SLOPE 0.2f

// ---------------- scratch (static device globals; no allocations) ------------
__device__ float d_h[NN * FF];
__device__ float d_xl[(size_t)NN * HF];
__device__ float d_xr[(size_t)NN * HF];
__device__ float d_logits[ET * HH];
__device__ float d_mx[NN * HH];
__device__ float d_den[NN * HH];
__device__ float d_alpha[ET * HH];
__device__ float d_agg[(size_t)NN * HF];
__device__ int   d_deg[NN];
__device__ int   d_rowptr[NN + 1];
__device__ int   d_cursor[NN];
__device__ int   d_elist[ET];

// ---------------- helpers ----------------------------------------------------
__device__ __forceinline__ void atomicMaxF(float* addr, float val) {
    if (val >= 0.0f) {
        atomicMax((int*)addr, __float_as_int(val));
    } else {
        atomicMin((unsigned int*)addr, __float_as_uint(val));
    }
}

__device__ __forceinline__ int edge_src(const int* ei, int e) {
    return (e < EE) ? ei[e] : (e - EE);
}
__device__ __forceinline__ int edge_dst(const int* ei, int e) {
    return (e < EE) ? ei[EE + e] : (e - EE);
}

// ---------------- stage 1: fc1 (3->3 1x1 conv) + BN1 -------------------------
__global__ void fc1_bn_kernel(const float* __restrict__ x,
                              const float* __restrict__ W,
                              const float* __restrict__ b,
                              const float* __restrict__ bg,
                              const float* __restrict__ bb,
                              const float* __restrict__ bm,
                              const float* __restrict__ bv) {
    int n = blockIdx.x;
    int p = blockIdx.y * 256 + threadIdx.x;
    float xin[CC];
#pragma unroll
    for (int c = 0; c < CC; c++) xin[c] = x[(size_t)n * FF + c * PIX + p];
#pragma unroll
    for (int oc = 0; oc < CC; oc++) {
        float t = b[oc];
#pragma unroll
        for (int ic = 0; ic < CC; ic++) t += W[oc * CC + ic] * xin[ic];
        float inv = bg[oc] * rsqrtf(bv[oc] + BEPS);
        d_h[(size_t)n * FF + oc * PIX + p] = t * inv + bb[oc] - bm[oc] * inv;
    }
}

// ---------------- init small state -------------------------------------------
__global__ void init_kernel() {
    int i = blockIdx.x * blockDim.x + threadIdx.x;
    if (i < NN * HH) {
        d_mx[i] = -INFINITY;
        d_den[i] = 0.0f;
    }
    if (i < NN) d_deg[i] = 0;
}

// ---------------- stage 2: SGEMM  C[M=512,N=12288] = d_h @ B + bias ---------
// BM=128 BN=128 BK=16, 256 threads, 8x8 microtile
__global__ void __launch_bounds__(256)
sgemm_kernel(const float* __restrict__ B, const float* __restrict__ bias, int which) {
    const int K = FF, Nc = HF;
    float* __restrict__ C = which ? d_xr : d_xl;
    const float* __restrict__ A = d_h;

    __shared__ float As[16][128];
    __shared__ float Bs[16][128];

    int tid  = threadIdx.x;
    int brow = blockIdx.y * 128;
    int bcol = blockIdx.x * 128;
    int trow = (tid >> 4) * 8;
    int tcol = (tid & 15) * 8;

    float acc[8][8];
#pragma unroll
    for (int i = 0; i < 8; i++)
#pragma unroll
        for (int j = 0; j < 8; j++) acc[i][j] = 0.0f;

    for (int k0 = 0; k0 < K; k0 += 16) {
#pragma unroll
        for (int i = 0; i < 2; i++) {
            int f = tid + 256 * i;
            // A tile: 128 rows x 16 k
            int r  = f >> 2;
            int kk = (f & 3) * 4;
            float4 va = *(const float4*)(A + (size_t)(brow + r) * K + k0 + kk);
            As[kk + 0][r] = va.x;
            As[kk + 1][r] = va.y;
            As[kk + 2][r] = va.z;
            As[kk + 3][r] = va.w;
            // B tile: 16 k-rows x 128 cols
            int bk = f >> 5;
            int bc = (f & 31) * 4;
            float4 vb = *(const float4*)(B + (size_t)(k0 + bk) * Nc + bcol + bc);
            *(float4*)&Bs[bk][bc] = vb;
        }
        __syncthreads();
#pragma unroll
        for (int kk = 0; kk < 16; kk++) {
            float af[8], bf[8];
#pragma unroll
            for (int i = 0; i < 8; i++) af[i] = As[kk][trow + i];
#pragma unroll
            for (int j = 0; j < 8; j++) bf[j] = Bs[kk][tcol + j];
#pragma unroll
            for (int i = 0; i < 8; i++)
#pragma unroll
                for (int j = 0; j < 8; j++) acc[i][j] += af[i] * bf[j];
        }
        __syncthreads();
    }

#pragma unroll
    for (int i = 0; i < 8; i++) {
#pragma unroll
        for (int j = 0; j < 8; j += 4) {
            float4 v;
            v.x = acc[i][j + 0] + bias[bcol + tcol + j + 0];
            v.y = acc[i][j + 1] + bias[bcol + tcol + j + 1];
            v.z = acc[i][j + 2] + bias[bcol + tcol + j + 2];
            v.w = acc[i][j + 3] + bias[bcol + tcol + j + 3];
            *(float4*)(C + (size_t)(brow + trow + i) * Nc + bcol + tcol + j) = v;
        }
    }
}

// ---------------- stage 3: GATv2 edge logits ---------------------------------
// grid = ET blocks, 128 threads (1 warp per head)
__global__ void logits_kernel(const int* __restrict__ ei, const float* __restrict__ att) {
    int e    = blockIdx.x;
    int h    = threadIdx.x >> 5;
    int lane = threadIdx.x & 31;
    int src = edge_src(ei, e);
    int dst = edge_dst(ei, e);
    const float4* pl = (const float4*)(d_xl + (size_t)src * HF + h * FF);
    const float4* pr = (const float4*)(d_xr + (size_t)dst * HF + h * FF);
    const float4* pa = (const float4*)(att + h * FF);
    float s = 0.0f;
#pragma unroll 4
    for (int it = 0; it < 24; it++) {
        int idx = lane + it * 32;
        float4 a = pl[idx];
        float4 b = pr[idx];
        float4 w = pa[idx];
        float z;
        z = a.x + b.x; s += w.x * (z > 0.0f ? z : SLOPE * z);
        z = a.y + b.y; s += w.y * (z > 0.0f ? z : SLOPE * z);
        z = a.z + b.z; s += w.z * (z > 0.0f ? z : SLOPE * z);
        z = a.w + b.w; s += w.w * (z > 0.0f ? z : SLOPE * z);
    }
#pragma unroll
    for (int o = 16; o; o >>= 1) s += __shfl_xor_sync(0xFFFFFFFFu, s, o);
    if (lane == 0) d_logits[e * HH + h] = s;
}

// ---------------- stage 4: segment softmax -----------------------------------
__global__ void segmax_kernel(const int* __restrict__ ei) {
    int i = blockIdx.x * blockDim.x + threadIdx.x;
    if (i >= ET * HH) return;
    int e = i >> 2, h = i & 3;
    int dst = edge_dst(ei, e);
    atomicMaxF(&d_mx[dst * HH + h], d_logits[i]);
}

__global__ void segexp_kernel(const int* __restrict__ ei) {
    int i = blockIdx.x * blockDim.x + threadIdx.x;
    if (i >= ET * HH) return;
    int e = i >> 2, h = i & 3;
    int dst = edge_dst(ei, e);
    float ex = expf(d_logits[i] - d_mx[dst * HH + h]);
    d_alpha[i] = ex;
    atomicAdd(&d_den[dst * HH + h], ex);
}

__global__ void segdiv_kernel(const int* __restrict__ ei) {
    int i = blockIdx.x * blockDim.x + threadIdx.x;
    if (i >= ET * HH) return;
    int e = i >> 2, h = i & 3;
    int dst = edge_dst(ei, e);
    d_alpha[i] = d_alpha[i] / d_den[dst * HH + h];
}

// ---------------- CSR build (by dst) -----------------------------------------
__global__ void deg_kernel(const int* __restrict__ ei) {
    int e = blockIdx.x * blockDim.x + threadIdx.x;
    if (e >= ET) return;
    atomicAdd(&d_deg[edge_dst(ei, e)], 1);
}

__global__ void scan_kernel() {
    __shared__ int s[NN];
    int t = threadIdx.x;
    s[t] = d_deg[t];
    __syncthreads();
    for (int o = 1; o < NN; o <<= 1) {
        int v = (t >= o) ? s[t - o] : 0;
        __syncthreads();
        s[t] += v;
        __syncthreads();
    }
    if (t == 0) d_rowptr[0] = 0;
    d_rowptr[t + 1] = s[t];
    d_cursor[t] = s[t] - d_deg[t];
}

__global__ void scatter_kernel(const int* __restrict__ ei) {
    int e = blockIdx.x * blockDim.x + threadIdx.x;
    if (e >= ET) return;
    int dst  = edge_dst(ei, e);
    int slot = atomicAdd(&d_cursor[dst], 1);
    d_elist[slot] = e;
}

// ---------------- stage 5: aggregation gather --------------------------------
// grid (NN, 12) : node n, chunk of 1024 features (head h = chunk/3)
__global__ void agg_kernel(const int* __restrict__ ei) {
    int n = blockIdx.x;
    int chunk = blockIdx.y;
    int h = chunk / CC;
    int foff = chunk * PIX + threadIdx.x * 4;
    float4 acc = make_float4(0.f, 0.f, 0.f, 0.f);
    int s0 = d_rowptr[n], s1 = d_rowptr[n + 1];
    for (int s = s0; s < s1; s++) {
        int e = d_elist[s];
        int src = edge_src(ei, e);
        float al = d_alpha[e * HH + h];
        float4 v = *(const float4*)(d_xl + (size_t)src * HF + foff);
        acc.x += al * v.x;
        acc.y += al * v.y;
        acc.z += al * v.z;
        acc.w += al * v.w;
    }
    *(float4*)(d_agg + (size_t)n * HF + foff) = acc;
}

// ---------------- stage 6: fc2+BN2+residual + FFN (fused) --------------------
__global__ void final_kernel(const float* __restrict__ x,
                             const float* __restrict__ gat_b,
                             const float* __restrict__ fc2W, const float* __restrict__ fc2b,
                             const float* __restrict__ b2g, const float* __restrict__ b2b,
                             const float* __restrict__ b2m, const float* __restrict__ b2v,
                             const float* __restrict__ f1W, const float* __restrict__ f1b,
                             const float* __restrict__ bf1g, const float* __restrict__ bf1b,
                             const float* __restrict__ bf1m, const float* __restrict__ bf1v,
                             const float* __restrict__ f2W, const float* __restrict__ f2b,
                             const float* __restrict__ bf2g, const float* __restrict__ bf2b,
                             const float* __restrict__ bf2m, const float* __restrict__ bf2v,
                             float* __restrict__ out) {
    int n = blockIdx.x;
    int p = blockIdx.y * 256 + threadIdx.x;

    float ch[HH * CC];
#pragma unroll
    for (int h = 0; h < HH; h++)
#pragma unroll
        for (int c = 0; c < CC; c++)
            ch[h * CC + c] = d_agg[(size_t)n * HF + h * FF + c * PIX + p]
                           + gat_b[h * FF + c * PIX + p];

    float gv[CC];
#pragma unroll
    for (int oc = 0; oc < CC; oc++) {
        float t = fc2b[oc];
#pragma unroll
        for (int k = 0; k < HH * CC; k++) t += fc2W[oc * (HH * CC) + k] * ch[k];
        float inv = b2g[oc] * rsqrtf(b2v[oc] + BEPS);
        gv[oc] = t * inv + b2b[oc] - b2m[oc] * inv + x[(size_t)n * FF + oc * PIX + p];
    }

    float f1[CC];
#pragma unroll
    for (int oc = 0; oc < CC; oc++) {
        float t = f1b[oc];
#pragma unroll
        for (int ic = 0; ic < CC; ic++) t += f1W[oc * CC + ic] * gv[ic];
        float inv = bf1g[oc] * rsqrtf(bf1v[oc] + BEPS);
        float val = t * inv + bf1b[oc] - bf1m[oc] * inv;
        f1[oc] = val > 0.0f ? val : 0.0f;
    }

#pragma unroll
    for (int oc = 0; oc < CC; oc++) {
        float t = f2b[oc];
#pragma unroll
        for (int ic = 0; ic < CC; ic++) t += f2W[oc * CC + ic] * f1[ic];
        float inv = bf2g[oc] * rsqrtf(bf2v[oc] + BEPS);
        float val = t * inv + bf2b[oc] - bf2m[oc] * inv;
        out[(size_t)n * FF + oc * PIX + p] = val + gv[oc];
    }
}

// ---------------- launch -----------------------------------------------------
extern "C" void kernel_launch(void* const* d_in, const int* in_sizes, int n_in,
                              void* d_out, int out_size) {
    const float* x     = (const float*)d_in[0];
    const int*   ei    = (const int*)d_in[1];
    const float* fc1W  = (const float*)d_in[2];
    const float* fc1b  = (const float*)d_in[3];
    const float* b1g   = (const float*)d_in[4];
    const float* b1b   = (const float*)d_in[5];
    const float* b1m   = (const float*)d_in[6];
    const float* b1v   = (const float*)d_in[7];
    const float* Wl    = (const float*)d_in[8];
    const float* bl    = (const float*)d_in[9];
    const float* Wr    = (const float*)d_in[10];
    const float* br    = (const float*)d_in[11];
    const float* att   = (const float*)d_in[12];
    const float* gat_b = (const float*)d_in[13];
    const float* fc2W  = (const float*)d_in[14];
    const float* fc2b  = (const float*)d_in[15];
    const float* b2g   = (const float*)d_in[16];
    const float* b2b   = (const float*)d_in[17];
    const float* b2m   = (const float*)d_in[18];
    const float* b2v   = (const float*)d_in[19];
    const float* f1W   = (const float*)d_in[20];
    const float* f1b   = (const float*)d_in[21];
    const float* bf1g  = (const float*)d_in[22];
    const float* bf1b  = (const float*)d_in[23];
    const float* bf1m  = (const float*)d_in[24];
    const float* bf1v  = (const float*)d_in[25];
    const float* f2W   = (const float*)d_in[26];
    const float* f2b   = (const float*)d_in[27];
    const float* bf2g  = (const float*)d_in[28];
    const float* bf2b  = (const float*)d_in[29];
    const float* bf2m  = (const float*)d_in[30];
    const float* bf2v  = (const float*)d_in[31];
    float* out = (float*)d_out;

    // 1. fc1 + BN1 -> d_h
    fc1_bn_kernel<<<dim3(NN, 4), 256>>>(x, fc1W, fc1b, b1g, b1b, b1m, b1v);
    // init softmax state + degree counters
    init_kernel<<<8, 256>>>();
    deg_kernel<<<(ET + 255) / 256, 256>>>(ei);
    // 2. xl = h@Wl+bl ; xr = h@Wr+br
    sgemm_kernel<<<dim3(HF / 128, NN / 128), 256>>>(Wl, bl, 0);
    sgemm_kernel<<<dim3(HF / 128, NN / 128), 256>>>(Wr, br, 1);
    // 3. edge logits
    logits_kernel<<<ET, 128>>>(ei, att);
    // 4. segment softmax
    segmax_kernel<<<(ET * HH + 255) / 256, 256>>>(ei);
    segexp_kernel<<<(ET * HH + 255) / 256, 256>>>(ei);
    segdiv_kernel<<<(ET * HH + 255) / 256, 256>>>(ei);
    // CSR by dst
    scan_kernel<<<1, NN>>>();
    scatter_kernel<<<(ET + 255) / 256, 256>>>(ei);
    // 5. aggregation
    agg_kernel<<<dim3(NN, HH * CC), 256>>>(ei);
    // 6. fused epilogue
    final_kernel<<<dim3(NN, 4), 256>>>(x, gat_b, fc2W, fc2b, b2g, b2b, b2m, b2v,
                                       f1W, f1b, bf1g, bf1b, bf1m, bf1v,
                                       f2W, f2b, bf2g, bf2b, bf2m, bf2v, out);
}

// round 3
// speedup vs baseline: 2.7871x; 2.7871x over previous
#include <cuda_runtime.h>
#include <cuda_bf16.h>
#include <math.h>
#include <stdint.h>

#define NN 512
#define CC 3
#define PIX 1024
#define FF 3072          // K dim
#define HH 4
#define HF 12288         // N dim
#define EE 4096
#define ET 4608
#define BEPS 1e-5f
#define SLOPE 0.2f

// GEMM tiling
#define BM 128
#define BN 128
#define BK 32
#define NK (FF / BK)             // 96
#define TILES_PER_GEMM ((NN / BM) * (HF / BN))   // 4 * 96 = 384

// smem stage layout (bf16, padded rows for conflict-free ldmatrix)
#define A_STRIDE 80              // 32 bf16 padded to 40 -> 80 B rows (16B-mult)
#define B_STRIDE 272             // 128 bf16 padded to 136 -> 272 B rows
#define OFF_AHI 0
#define OFF_ALO (BM * A_STRIDE)                  // 10240
#define OFF_BHI (2 * BM * A_STRIDE)              // 20480
#define OFF_BLO (OFF_BHI + BK * B_STRIDE)        // 29184
#define STAGE_BYTES (OFF_BLO + BK * B_STRIDE)    // 37888
#define NSTAGE 3
#define SMEM_TOTAL (NSTAGE * STAGE_BYTES)        // 113664

// ---------------- scratch (static device globals; no allocations) ------------
__device__ __nv_bfloat16 d_Ah[NN * FF];
__device__ __nv_bfloat16 d_Al[NN * FF];
__device__ __nv_bfloat16 d_Blh[(size_t)FF * HF];
__device__ __nv_bfloat16 d_Bll[(size_t)FF * HF];
__device__ __nv_bfloat16 d_Brh[(size_t)FF * HF];
__device__ __nv_bfloat16 d_Brl[(size_t)FF * HF];
__device__ float d_xl[(size_t)NN * HF];
__device__ float d_xr[(size_t)NN * HF];
__device__ float d_logits[ET * HH];
__device__ float d_mx[NN * HH];
__device__ float d_den[NN * HH];
__device__ float d_alpha[ET * HH];
__device__ float d_agg[(size_t)NN * HF];
__device__ int   d_deg[NN];
__device__ int   d_rowptr[NN + 1];
__device__ int   d_cursor[NN];
__device__ int   d_elist[ET];

// ---------------- PTX helpers ------------------------------------------------
__device__ __forceinline__ uint32_t smem_to_u32(const void* p) {
    uint32_t a;
    asm("{ .reg .u64 t; cvta.to.shared.u64 t, %1; cvt.u32.u64 %0, t; }" : "=r"(a) : "l"(p));
    return a;
}
__device__ __forceinline__ void cpa16(uint32_t dst, const void* src) {
    asm volatile("cp.async.cg.shared.global [%0], [%1], 16;" :: "r"(dst), "l"(src));
}
#define CP_COMMIT() asm volatile("cp.async.commit_group;" ::: "memory")
#define CP_WAIT0()  asm volatile("cp.async.wait_group 0;" ::: "memory")
#define CP_WAIT1()  asm volatile("cp.async.wait_group 1;" ::: "memory")

#define LDSM_X4(r0, r1, r2, r3, addr) \
    asm volatile("ldmatrix.sync.aligned.m8n8.x4.shared.b16 {%0,%1,%2,%3}, [%4];" \
        : "=r"(r0), "=r"(r1), "=r"(r2), "=r"(r3) : "r"(addr))
#define LDSM_X4T(r0, r1, r2, r3, addr) \
    asm volatile("ldmatrix.sync.aligned.m8n8.x4.trans.shared.b16 {%0,%1,%2,%3}, [%4];" \
        : "=r"(r0), "=r"(r1), "=r"(r2), "=r"(r3) : "r"(addr))

#define MMA16816(d, a, b) \
    asm volatile("mma.sync.aligned.m16n8k16.row.col.f32.bf16.bf16.f32 " \
        "{%0,%1,%2,%3}, {%4,%5,%6,%7}, {%8,%9}, {%0,%1,%2,%3};" \
        : "+f"((d)[0]), "+f"((d)[1]), "+f"((d)[2]), "+f"((d)[3]) \
        : "r"((a)[0]), "r"((a)[1]), "r"((a)[2]), "r"((a)[3]), "r"((b)[0]), "r"((b)[1]))

// ---------------- misc helpers ----------------------------------------------
__device__ __forceinline__ void atomicMaxF(float* addr, float val) {
    if (val >= 0.0f) atomicMax((int*)addr, __float_as_int(val));
    else             atomicMin((unsigned int*)addr, __float_as_uint(val));
}
__device__ __forceinline__ int edge_src(const int* ei, int e) { return (e < EE) ? ei[e] : (e - EE); }
__device__ __forceinline__ int edge_dst(const int* ei, int e) { return (e < EE) ? ei[EE + e] : (e - EE); }

// ---------------- stage 1: fc1 + BN1 -> bf16 hi/lo ---------------------------
__global__ void fc1_bn_kernel(const float* __restrict__ x,
                              const float* __restrict__ W,
                              const float* __restrict__ b,
                              const float* __restrict__ bg,
                              const float* __restrict__ bb,
                              const float* __restrict__ bm,
                              const float* __restrict__ bv) {
    int n = blockIdx.x;
    int p = blockIdx.y * 256 + threadIdx.x;
    float xin[CC];
#pragma unroll
    for (int c = 0; c < CC; c++) xin[c] = x[(size_t)n * FF + c * PIX + p];
#pragma unroll
    for (int oc = 0; oc < CC; oc++) {
        float t = b[oc];
#pragma unroll
        for (int ic = 0; ic < CC; ic++) t += W[oc * CC + ic] * xin[ic];
        float inv = bg[oc] * rsqrtf(bv[oc] + BEPS);
        float hv = t * inv + bb[oc] - bm[oc] * inv;
        __nv_bfloat16 hi = __float2bfloat16(hv);
        size_t o = (size_t)n * FF + oc * PIX + p;
        d_Ah[o] = hi;
        d_Al[o] = __float2bfloat16(hv - __bfloat162float(hi));
    }
}

// ---------------- weight bf16 hi/lo split (no transpose needed) --------------
__global__ void wsplit_kernel(const float* __restrict__ Wl, const float* __restrict__ Wr) {
    const float* W = blockIdx.y ? Wr : Wl;
    __nv_bfloat16* Bh = blockIdx.y ? d_Brh : d_Blh;
    __nv_bfloat16* Bl = blockIdx.y ? d_Brl : d_Bll;
    size_t i = ((size_t)blockIdx.x * 256 + threadIdx.x) * 4;
    float4 v = *(const float4*)(W + i);
    __nv_bfloat16 h0 = __float2bfloat16(v.x);
    __nv_bfloat16 h1 = __float2bfloat16(v.y);
    __nv_bfloat16 h2 = __float2bfloat16(v.z);
    __nv_bfloat16 h3 = __float2bfloat16(v.w);
    __nv_bfloat162* ph = (__nv_bfloat162*)(Bh + i);
    ph[0] = __nv_bfloat162(h0, h1);
    ph[1] = __nv_bfloat162(h2, h3);
    __nv_bfloat162* pl = (__nv_bfloat162*)(Bl + i);
    pl[0] = __nv_bfloat162(__float2bfloat16(v.x - __bfloat162float(h0)),
                           __float2bfloat16(v.y - __bfloat162float(h1)));
    pl[1] = __nv_bfloat162(__float2bfloat16(v.z - __bfloat162float(h2)),
                           __float2bfloat16(v.w - __bfloat162float(h3)));
}

// ---------------- init small state -------------------------------------------
__global__ void init_kernel() {
    int i = blockIdx.x * blockDim.x + threadIdx.x;
    if (i < NN * HH) { d_mx[i] = -INFINITY; d_den[i] = 0.0f; }
    if (i < NN) d_deg[i] = 0;
}

// ---------------- stage 2: HMMA GEMM -----------------------------------------
__device__ __forceinline__ void load_stage(uint32_t st, int m0, int n0, int k0,
                                           const __nv_bfloat16* __restrict__ Bh,
                                           const __nv_bfloat16* __restrict__ Bl,
                                           int tid) {
#pragma unroll
    for (int i = tid; i < 512; i += 256) {
        int row = i >> 2, c = i & 3;
        uint32_t off = row * A_STRIDE + c * 16;
        size_t g = (size_t)(m0 + row) * FF + k0 + c * 8;
        cpa16(st + OFF_AHI + off, d_Ah + g);
        cpa16(st + OFF_ALO + off, d_Al + g);
    }
#pragma unroll
    for (int i = tid; i < 512; i += 256) {
        int row = i >> 4, c = i & 15;
        uint32_t off = row * B_STRIDE + c * 16;
        size_t g = (size_t)(k0 + row) * HF + n0 + c * 8;
        cpa16(st + OFF_BHI + off, Bh + g);
        cpa16(st + OFF_BLO + off, Bl + g);
    }
}

__global__ void __launch_bounds__(256)
mmagemm_kernel(const float* __restrict__ biasL, const float* __restrict__ biasR) {
    extern __shared__ __align__(1024) char smem[];
    uint32_t sbase = smem_to_u32(smem);
    int tid = threadIdx.x;
    int wid = tid >> 5, lane = tid & 31;

    int bid = blockIdx.x;
    int gemm = (bid >= TILES_PER_GEMM) ? 1 : 0;
    int r = bid - gemm * TILES_PER_GEMM;
    int n0 = (r >> 2) * BN;
    int m0 = (r & 3) * BM;

    const __nv_bfloat16* Bh = gemm ? d_Brh : d_Blh;
    const __nv_bfloat16* Bl = gemm ? d_Brl : d_Bll;
    float* C = gemm ? d_xr : d_xl;
    const float* bias = gemm ? biasR : biasL;

    int wm = (wid & 1) * 64;       // warp m offset (2 warps in m)
    int wn = (wid >> 1) * 32;      // warp n offset (4 warps in n)

    uint32_t stg[NSTAGE];
#pragma unroll
    for (int s = 0; s < NSTAGE; s++) stg[s] = sbase + s * STAGE_BYTES;

    float acc[4][4][4];
#pragma unroll
    for (int mf = 0; mf < 4; mf++)
#pragma unroll
        for (int nf = 0; nf < 4; nf++)
#pragma unroll
            for (int q = 0; q < 4; q++) acc[mf][nf][q] = 0.0f;

    // prologue: stages 0 and 1
    load_stage(stg[0], m0, n0, 0, Bh, Bl, tid);
    CP_COMMIT();
    load_stage(stg[1], m0, n0, BK, Bh, Bl, tid);
    CP_COMMIT();

    // ldmatrix per-lane base offsets
    uint32_t a_lrow = (lane & 7) + ((lane >> 3) & 1) * 8;   // row within 16
    uint32_t a_kadd = (lane >> 4) * 16;                     // bytes (k halves)
    uint32_t b_lrow = (lane & 7) + ((lane >> 3) & 1) * 8;   // k row within 16
    uint32_t b_nadd = (lane >> 4) * 16;                     // bytes (n halves)

    for (int kt = 0; kt < NK; kt++) {
        if (kt + 2 < NK) { CP_WAIT1(); } else { CP_WAIT0(); }
        __syncthreads();
        if (kt + 2 < NK) {
            load_stage(stg[(kt + 2) % NSTAGE], m0, n0, (kt + 2) * BK, Bh, Bl, tid);
            CP_COMMIT();
        }
        uint32_t st = stg[kt % NSTAGE];
#pragma unroll
        for (int kk = 0; kk < BK; kk += 16) {
            uint32_t ahi[4][4], alo[4][4], bhi[4][2], blo[4][2];
            uint32_t abase = st + (wm + a_lrow) * A_STRIDE + kk * 2 + a_kadd;
#pragma unroll
            for (int mf = 0; mf < 4; mf++) {
                uint32_t ad = abase + mf * 16 * A_STRIDE;
                LDSM_X4(ahi[mf][0], ahi[mf][1], ahi[mf][2], ahi[mf][3], ad + OFF_AHI);
                LDSM_X4(alo[mf][0], alo[mf][1], alo[mf][2], alo[mf][3], ad + OFF_ALO);
            }
            uint32_t bbase = st + (kk + b_lrow) * B_STRIDE + wn * 2 + b_nadd;
            LDSM_X4T(bhi[0][0], bhi[0][1], bhi[1][0], bhi[1][1], bbase + OFF_BHI);
            LDSM_X4T(bhi[2][0], bhi[2][1], bhi[3][0], bhi[3][1], bbase + OFF_BHI + 32);
            LDSM_X4T(blo[0][0], blo[0][1], blo[1][0], blo[1][1], bbase + OFF_BLO);
            LDSM_X4T(blo[2][0], blo[2][1], blo[3][0], blo[3][1], bbase + OFF_BLO + 32);
#pragma unroll
            for (int mf = 0; mf < 4; mf++)
#pragma unroll
                for (int nf = 0; nf < 4; nf++) {
                    MMA16816(acc[mf][nf], ahi[mf], bhi[nf]);
                    MMA16816(acc[mf][nf], ahi[mf], blo[nf]);
                    MMA16816(acc[mf][nf], alo[mf], bhi[nf]);
                }
        }
    }

    // epilogue: bias add + store
    int g = lane >> 2, tc = lane & 3;
#pragma unroll
    for (int mf = 0; mf < 4; mf++) {
#pragma unroll
        for (int nf = 0; nf < 4; nf++) {
            int row = m0 + wm + mf * 16 + g;
            int col = n0 + wn + nf * 8 + tc * 2;
            float b0 = bias[col], b1 = bias[col + 1];
            float2 v0 = make_float2(acc[mf][nf][0] + b0, acc[mf][nf][1] + b1);
            float2 v1 = make_float2(acc[mf][nf][2] + b0, acc[mf][nf][3] + b1);
            *(float2*)(C + (size_t)row * HF + col) = v0;
            *(float2*)(C + (size_t)(row + 8) * HF + col) = v1;
        }
    }
}

// ---------------- stage 3: GATv2 edge logits ---------------------------------
__global__ void logits_kernel(const int* __restrict__ ei, const float* __restrict__ att) {
    int e    = blockIdx.x;
    int h    = threadIdx.x >> 5;
    int lane = threadIdx.x & 31;
    int src = edge_src(ei, e);
    int dst = edge_dst(ei, e);
    const float4* pl = (const float4*)(d_xl + (size_t)src * HF + h * FF);
    const float4* pr = (const float4*)(d_xr + (size_t)dst * HF + h * FF);
    const float4* pa = (const float4*)(att + h * FF);
    float s = 0.0f;
#pragma unroll 4
    for (int it = 0; it < 24; it++) {
        int idx = lane + it * 32;
        float4 a = pl[idx];
        float4 b = pr[idx];
        float4 w = pa[idx];
        float z;
        z = a.x + b.x; s += w.x * (z > 0.0f ? z : SLOPE * z);
        z = a.y + b.y; s += w.y * (z > 0.0f ? z : SLOPE * z);
        z = a.z + b.z; s += w.z * (z > 0.0f ? z : SLOPE * z);
        z = a.w + b.w; s += w.w * (z > 0.0f ? z : SLOPE * z);
    }
#pragma unroll
    for (int o = 16; o; o >>= 1) s += __shfl_xor_sync(0xFFFFFFFFu, s, o);
    if (lane == 0) d_logits[e * HH + h] = s;
}

// ---------------- stage 4: segment softmax -----------------------------------
__global__ void segmax_kernel(const int* __restrict__ ei) {
    int i = blockIdx.x * blockDim.x + threadIdx.x;
    if (i >= ET * HH) return;
    int e = i >> 2, h = i & 3;
    atomicMaxF(&d_mx[edge_dst(ei, e) * HH + h], d_logits[i]);
}
__global__ void segexp_kernel(const int* __restrict__ ei) {
    int i = blockIdx.x * blockDim.x + threadIdx.x;
    if (i >= ET * HH) return;
    int e = i >> 2, h = i & 3;
    int dst = edge_dst(ei, e);
    float ex = expf(d_logits[i] - d_mx[dst * HH + h]);
    d_alpha[i] = ex;
    atomicAdd(&d_den[dst * HH + h], ex);
}
__global__ void segdiv_kernel(const int* __restrict__ ei) {
    int i = blockIdx.x * blockDim.x + threadIdx.x;
    if (i >= ET * HH) return;
    int e = i >> 2, h = i & 3;
    d_alpha[i] = d_alpha[i] / d_den[edge_dst(ei, e) * HH + h];
}

// ---------------- CSR build (by dst) -----------------------------------------
__global__ void deg_kernel(const int* __restrict__ ei) {
    int e = blockIdx.x * blockDim.x + threadIdx.x;
    if (e >= ET) return;
    atomicAdd(&d_deg[edge_dst(ei, e)], 1);
}
__global__ void scan_kernel() {
    __shared__ int s[NN];
    int t = threadIdx.x;
    s[t] = d_deg[t];
    __syncthreads();
    for (int o = 1; o < NN; o <<= 1) {
        int v = (t >= o) ? s[t - o] : 0;
        __syncthreads();
        s[t] += v;
        __syncthreads();
    }
    if (t == 0) d_rowptr[0] = 0;
    d_rowptr[t + 1] = s[t];
    d_cursor[t] = s[t] - d_deg[t];
}
__global__ void scatter_kernel(const int* __restrict__ ei) {
    int e = blockIdx.x * blockDim.x + threadIdx.x;
    if (e >= ET) return;
    int slot = atomicAdd(&d_cursor[edge_dst(ei, e)], 1);
    d_elist[slot] = e;
}

// ---------------- stage 5: aggregation gather --------------------------------
__global__ void agg_kernel(const int* __restrict__ ei) {
    int n = blockIdx.x;
    int chunk = blockIdx.y;
    int h = chunk / CC;
    int foff = chunk * PIX + threadIdx.x * 4;
    float4 acc = make_float4(0.f, 0.f, 0.f, 0.f);
    int s0 = d_rowptr[n], s1 = d_rowptr[n + 1];
    for (int s = s0; s < s1; s++) {
        int e = d_elist[s];
        int src = edge_src(ei, e);
        float al = d_alpha[e * HH + h];
        float4 v = *(const float4*)(d_xl + (size_t)src * HF + foff);
        acc.x += al * v.x;
        acc.y += al * v.y;
        acc.z += al * v.z;
        acc.w += al * v.w;
    }
    *(float4*)(d_agg + (size_t)n * HF + foff) = acc;
}

// ---------------- stage 6: fc2+BN2+residual + FFN (fused) --------------------
__global__ void final_kernel(const float* __restrict__ x,
                             const float* __restrict__ gat_b,
                             const float* __restrict__ fc2W, const float* __restrict__ fc2b,
                             const float* __restrict__ b2g, const float* __restrict__ b2b,
                             const float* __restrict__ b2m, const float* __restrict__ b2v,
                             const float* __restrict__ f1W, const float* __restrict__ f1b,
                             const float* __restrict__ bf1g, const float* __restrict__ bf1b,
                             const float* __restrict__ bf1m, const float* __restrict__ bf1v,
                             const float* __restrict__ f2W, const float* __restrict__ f2b,
                             const float* __restrict__ bf2g, const float* __restrict__ bf2b,
                             const float* __restrict__ bf2m, const float* __restrict__ bf2v,
                             float* __restrict__ out) {
    int n = blockIdx.x;
    int p = blockIdx.y * 256 + threadIdx.x;

    float ch[HH * CC];
#pragma unroll
    for (int h = 0; h < HH; h++)
#pragma unroll
        for (int c = 0; c < CC; c++)
            ch[h * CC + c] = d_agg[(size_t)n * HF + h * FF + c * PIX + p]
                           + gat_b[h * FF + c * PIX + p];

    float gv[CC];
#pragma unroll
    for (int oc = 0; oc < CC; oc++) {
        float t = fc2b[oc];
#pragma unroll
        for (int k = 0; k < HH * CC; k++) t += fc2W[oc * (HH * CC) + k] * ch[k];
        float inv = b2g[oc] * rsqrtf(b2v[oc] + BEPS);
        gv[oc] = t * inv + b2b[oc] - b2m[oc] * inv + x[(size_t)n * FF + oc * PIX + p];
    }
    float f1[CC];
#pragma unroll
    for (int oc = 0; oc < CC; oc++) {
        float t = f1b[oc];
#pragma unroll
        for (int ic = 0; ic < CC; ic++) t += f1W[oc * CC + ic] * gv[ic];
        float inv = bf1g[oc] * rsqrtf(bf1v[oc] + BEPS);
        float val = t * inv + bf1b[oc] - bf1m[oc] * inv;
        f1[oc] = val > 0.0f ? val : 0.0f;
    }
#pragma unroll
    for (int oc = 0; oc < CC; oc++) {
        float t = f2b[oc];
#pragma unroll
        for (int ic = 0; ic < CC; ic++) t += f2W[oc * CC + ic] * f1[ic];
        float inv = bf2g[oc] * rsqrtf(bf2v[oc] + BEPS);
        float val = t * inv + bf2b[oc] - bf2m[oc] * inv;
        out[(size_t)n * FF + oc * PIX + p] = val + gv[oc];
    }
}

// ---------------- launch -----------------------------------------------------
extern "C" void kernel_launch(void* const* d_in, const int* in_sizes, int n_in,
                              void* d_out, int out_size) {
    const float* x     = (const float*)d_in[0];
    const int*   ei    = (const int*)d_in[1];
    const float* fc1W  = (const float*)d_in[2];
    const float* fc1b  = (const float*)d_in[3];
    const float* b1g   = (const float*)d_in[4];
    const float* b1b   = (const float*)d_in[5];
    const float* b1m   = (const float*)d_in[6];
    const float* b1v   = (const float*)d_in[7];
    const float* Wl    = (const float*)d_in[8];
    const float* bl    = (const float*)d_in[9];
    const float* Wr    = (const float*)d_in[10];
    const float* br    = (const float*)d_in[11];
    const float* att   = (const float*)d_in[12];
    const float* gat_b = (const float*)d_in[13];
    const float* fc2W  = (const float*)d_in[14];
    const float* fc2b  = (const float*)d_in[15];
    const float* b2g   = (const float*)d_in[16];
    const float* b2b   = (const float*)d_in[17];
    const float* b2m   = (const float*)d_in[18];
    const float* b2v   = (const float*)d_in[19];
    const float* f1W   = (const float*)d_in[20];
    const float* f1b   = (const float*)d_in[21];
    const float* bf1g  = (const float*)d_in[22];
    const float* bf1b  = (const float*)d_in[23];
    const float* bf1m  = (const float*)d_in[24];
    const float* bf1v  = (const float*)d_in[25];
    const float* f2W   = (const float*)d_in[26];
    const float* f2b   = (const float*)d_in[27];
    const float* bf2g  = (const float*)d_in[28];
    const float* bf2b  = (const float*)d_in[29];
    const float* bf2m  = (const float*)d_in[30];
    const float* bf2v  = (const float*)d_in[31];
    float* out = (float*)d_out;

    cudaFuncSetAttribute(mmagemm_kernel, cudaFuncAttributeMaxDynamicSharedMemorySize, SMEM_TOTAL);

    // weight hi/lo split (streaming, no transpose)
    wsplit_kernel<<<dim3((FF * HF) / (256 * 4), 2), 256>>>(Wl, Wr);
    // fc1 + BN1 -> A hi/lo
    fc1_bn_kernel<<<dim3(NN, 4), 256>>>(x, fc1W, fc1b, b1g, b1b, b1m, b1v);
    // init softmax state + degree counters
    init_kernel<<<8, 256>>>();
    deg_kernel<<<(ET + 255) / 256, 256>>>(ei);
    // HMMA GEMMs: xl and xr in one launch
    mmagemm_kernel<<<2 * TILES_PER_GEMM, 256, SMEM_TOTAL>>>(bl, br);
    // edge logits
    logits_kernel<<<ET, 128>>>(ei, att);
    // segment softmax
    segmax_kernel<<<(ET * HH + 255) / 256, 256>>>(ei);
    segexp_kernel<<<(ET * HH + 255) / 256, 256>>>(ei);
    segdiv_kernel<<<(ET * HH + 255) / 256, 256>>>(ei);
    // CSR by dst
    scan_kernel<<<1, NN>>>();
    scatter_kernel<<<(ET + 255) / 256, 256>>>(ei);
    // aggregation
    agg_kernel<<<dim3(NN, HH * CC), 256>>>(ei);
    // fused epilogue
    final_kernel<<<dim3(NN, 4), 256>>>(x, gat_b, fc2W, fc2b, b2g, b2b, b2m, b2v,
                                       f1W, f1b, bf1g, bf1b, bf1m, bf1v,
                                       f2W, f2b, bf2g, bf2b, bf2m, bf2v, out);
}